// round 16
// baseline (speedup 1.0000x reference)
#include <cuda_runtime.h>
#include <cuda_fp16.h>

#define NN   50000
#define EE   800000
#define INF  128
#define HH   4
#define OUTF 32
#define CC   128       // HH*OUTF
#define DSTR 64        // padded CSR stride (max in-degree; P(deg>=64) ~ 1e-20)

#define NSCAT 782      // ceil(800000/4/256) scatter blocks
#define NPROJ 782      // 391 node-tiles x 2 col-halves

// ---------------- scratch (device globals; no allocations) ----------------
__device__ __align__(16) __half g_hproj16[NN * CC];   // projected features, fp16
__device__ __align__(16) float  g_ssrc[NN * HH];
__device__ __align__(16) float  g_sdst[NN * HH];
__device__ int g_cnt[NN];           // in-degree (zero at load; k_gat re-zeros each run)
__device__ int g_esrc[NN * DSTR];   // padded CSR: src ids per dst

// ---------------- packed f32x2 helpers ----------------
__device__ __forceinline__ unsigned long long ffma2(unsigned long long a,
                                                    unsigned long long b,
                                                    unsigned long long c) {
    unsigned long long d;
    asm("fma.rn.f32x2 %0, %1, %2, %3;" : "=l"(d) : "l"(a), "l"(b), "l"(c));
    return d;
}
__device__ __forceinline__ void unpackf2(unsigned long long v, float& x, float& y) {
    asm("mov.b64 {%0, %1}, %2;" : "=f"(x), "=f"(y) : "l"(v));
}
__device__ __forceinline__ unsigned long long packf2(float x, float y) {
    unsigned long long d;
    asm("mov.b64 %0, {%1, %2};" : "=l"(d) : "f"(x), "f"(y));
    return d;
}

// ---------------- K1: interleaved scatter + projection GEMM + node scores ----------------
// Odd bids: scatter. Even bids: 128-node x 64-col GEMM half-tile.
// GEMM uses node-pair accumulators: H tile stored transposed [k][node] so each
// FFMA2 input pair is one LDS.64; W duplication costs only 4 packs per kk.
__global__ __launch_bounds__(256) void k_fused(const float* __restrict__ h,
                                               const int* __restrict__ ei,
                                               const float* __restrict__ W,
                                               const float* __restrict__ a) {
    __shared__ __align__(16) float Hst[16][130];  // [k][node] transposed (+pad)
    __shared__ __align__(16) float Ws[16][64];    // [k][col half]
    int tid = threadIdx.x;

    if (blockIdx.x & 1) {
        // ---- scatter ----
        int sb = blockIdx.x >> 1;
        int base = (sb * 256 + tid) * 4;
        if (base >= EE) return;
        int4 s = *(const int4*)&ei[base];
        int4 d = *(const int4*)&ei[EE + base];
        int p0 = min(atomicAdd(&g_cnt[d.x], 1), DSTR - 1);
        int p1 = min(atomicAdd(&g_cnt[d.y], 1), DSTR - 1);
        int p2 = min(atomicAdd(&g_cnt[d.z], 1), DSTR - 1);
        int p3 = min(atomicAdd(&g_cnt[d.w], 1), DSTR - 1);
        g_esrc[d.x * DSTR + p0] = s.x;
        g_esrc[d.y * DSTR + p1] = s.y;
        g_esrc[d.z * DSTR + p2] = s.z;
        g_esrc[d.w * DSTR + p3] = s.w;
        return;
    }

    int pb = blockIdx.x >> 1;
    int c = pb & 1;                  // col half: heads {2c, 2c+1}
    int node0 = (pb >> 1) * 128;
    int tx = tid & 15;
    int ty = tid >> 4;
    int tx2 = tx * 2;

    // acc2[pair][col]: pair p = nodes (ty*8+2p, ty*8+2p+1); col 0..3 =
    // local cols {tx2, tx2+1, 32+tx2, 32+tx2+1}
    unsigned long long acc2[4][4];
#pragma unroll
    for (int p = 0; p < 4; p++)
#pragma unroll
        for (int q = 0; q < 4; q++) acc2[p][q] = 0ull;

    int ln  = tid & 127;              // Hst loader node
    int lkb = (tid >> 7) * 8;         // Hst loader k base (0 or 8)
    int wk  = tid >> 4;               // Ws loader k
    int wc0 = (tid & 15) * 4;         // Ws loader col base (local)
    int gcol = c * 64 + wc0;
    int whd = gcol >> 5, wo0 = gcol & 31;

    for (int kb = 0; kb < INF; kb += 16) {
        {
            int node = node0 + ln;
            float4 a0, a1;
            if (node < NN) {
                a0 = *(const float4*)&h[node * INF + kb + lkb];
                a1 = *(const float4*)&h[node * INF + kb + lkb + 4];
            } else {
                a0 = make_float4(0, 0, 0, 0);
                a1 = a0;
            }
            // transposed store: conflict-free (ln consecutive across warp)
            Hst[lkb + 0][ln] = a0.x; Hst[lkb + 1][ln] = a0.y;
            Hst[lkb + 2][ln] = a0.z; Hst[lkb + 3][ln] = a0.w;
            Hst[lkb + 4][ln] = a1.x; Hst[lkb + 5][ln] = a1.y;
            Hst[lkb + 6][ln] = a1.z; Hst[lkb + 7][ln] = a1.w;
        }
        *(float4*)&Ws[wk][wc0] = *(const float4*)&W[(whd * INF + kb + wk) * OUTF + wo0];
        __syncthreads();
#pragma unroll
        for (int kk = 0; kk < 16; kk++) {
            float2 w01 = *(const float2*)&Ws[kk][tx2];
            float2 w23 = *(const float2*)&Ws[kk][32 + tx2];
            unsigned long long wd0 = packf2(w01.x, w01.x);
            unsigned long long wd1 = packf2(w01.y, w01.y);
            unsigned long long wd2 = packf2(w23.x, w23.x);
            unsigned long long wd3 = packf2(w23.y, w23.y);
#pragma unroll
            for (int p = 0; p < 4; p++) {
                unsigned long long h2 =
                    *(const unsigned long long*)&Hst[kk][ty * 8 + 2 * p];
                acc2[p][0] = ffma2(h2, wd0, acc2[p][0]);
                acc2[p][1] = ffma2(h2, wd1, acc2[p][1]);
                acc2[p][2] = ffma2(h2, wd2, acc2[p][2]);
                acc2[p][3] = ffma2(h2, wd3, acc2[p][3]);
            }
        }
        __syncthreads();
    }

    // ---- store hproj (fp16) + score epilogue ----
    float asv[2][2], adv[2][2];
#pragma unroll
    for (int j = 0; j < 2; j++) {
        int head = c * 2 + j;
        float2 v0 = *(const float2*)&a[head * 64 + tx2];
        float2 v1 = *(const float2*)&a[head * 64 + 32 + tx2];
        asv[j][0] = v0.x; asv[j][1] = v0.y;
        adv[j][0] = v1.x; adv[j][1] = v1.y;
    }

#pragma unroll
    for (int p = 0; p < 4; p++) {
        float va[4], vb[4];
#pragma unroll
        for (int q = 0; q < 4; q++) unpackf2(acc2[p][q], va[q], vb[q]);
        int nodeA = node0 + ty * 8 + 2 * p;
        int nodeB = nodeA + 1;

        if (nodeA < NN) {
            *(__half2*)&g_hproj16[nodeA * CC + c * 64 + tx2] =
                __floats2half2_rn(va[0], va[1]);
            *(__half2*)&g_hproj16[nodeA * CC + c * 64 + 32 + tx2] =
                __floats2half2_rn(va[2], va[3]);
        }
        if (nodeB < NN) {
            *(__half2*)&g_hproj16[nodeB * CC + c * 64 + tx2] =
                __floats2half2_rn(vb[0], vb[1]);
            *(__half2*)&g_hproj16[nodeB * CC + c * 64 + 32 + tx2] =
                __floats2half2_rn(vb[2], vb[3]);
        }

        float psA[2], pdA[2], psB[2], pdB[2];
        psA[0] = va[0] * asv[0][0] + va[1] * asv[0][1];
        psA[1] = va[2] * asv[1][0] + va[3] * asv[1][1];
        pdA[0] = va[0] * adv[0][0] + va[1] * adv[0][1];
        pdA[1] = va[2] * adv[1][0] + va[3] * adv[1][1];
        psB[0] = vb[0] * asv[0][0] + vb[1] * asv[0][1];
        psB[1] = vb[2] * asv[1][0] + vb[3] * asv[1][1];
        pdB[0] = vb[0] * adv[0][0] + vb[1] * adv[0][1];
        pdB[1] = vb[2] * adv[1][0] + vb[3] * adv[1][1];
#pragma unroll
        for (int off = 8; off; off >>= 1) {
#pragma unroll
            for (int j = 0; j < 2; j++) {
                psA[j] += __shfl_xor_sync(0xFFFFFFFFu, psA[j], off);
                pdA[j] += __shfl_xor_sync(0xFFFFFFFFu, pdA[j], off);
                psB[j] += __shfl_xor_sync(0xFFFFFFFFu, psB[j], off);
                pdB[j] += __shfl_xor_sync(0xFFFFFFFFu, pdB[j], off);
            }
        }
        if (tx == 0) {
            if (nodeA < NN) {
                *(float2*)&g_ssrc[nodeA * HH + c * 2] = make_float2(psA[0], psA[1]);
                *(float2*)&g_sdst[nodeA * HH + c * 2] = make_float2(pdA[0], pdA[1]);
            }
            if (nodeB < NN) {
                *(float2*)&g_ssrc[nodeB * HH + c * 2] = make_float2(psB[0], psB[1]);
                *(float2*)&g_sdst[nodeB * HH + c * 2] = make_float2(pdB[0], pdB[1]);
            }
        }
    }
}

// ---------------- K2: block-per-node (2 warps) softmax + aggregation + ELU ----------------
// (exact R15 version — measured 41.8 us)
__global__ __launch_bounds__(64) void k_gat(float* __restrict__ out) {
    const unsigned FULL = 0xFFFFFFFFu;
    __shared__ int   sOff[DSTR];        // src * CC
    __shared__ float sW[DSTR][HH];
    __shared__ float sDen[HH];
    __shared__ __align__(16) float sAcc[2][CC];

    int node = blockIdx.x;
    int tid  = threadIdx.x;
    int w    = tid >> 5;
    int lane = tid & 31;
    int hd   = lane >> 3;

    int cnt = min(g_cnt[node], DSTR);
    float4 sd4 = *(const float4*)&g_sdst[node * HH];

    // Phase A: slot j = w + lane*2; all 64 lanes cover all 64 slots
    int j = w + lane * 2;
    if (j < cnt) {
        int src = g_esrc[node * DSTR + j];
        float4 ss = *(const float4*)&g_ssrc[src * HH];
        float4 w0;
        float x;
        x = ss.x + sd4.x; x = x > 0.0f ? x : 0.2f * x; w0.x = __expf(x);
        x = ss.y + sd4.y; x = x > 0.0f ? x : 0.2f * x; w0.y = __expf(x);
        x = ss.z + sd4.z; x = x > 0.0f ? x : 0.2f * x; w0.z = __expf(x);
        x = ss.w + sd4.w; x = x > 0.0f ? x : 0.2f * x; w0.w = __expf(x);
        sOff[j] = src * CC;
        *(float4*)&sW[j][0] = w0;
    } else {
        sOff[j] = 0;
        *(float4*)&sW[j][0] = make_float4(0, 0, 0, 0);
    }
    __syncthreads();
    if (tid == 0) g_cnt[node] = 0;   // restore zero invariant (all reads done)

    // denominator: warp w reduces heads {2w, 2w+1} over zero-filled slots
    float2 d0 = *(const float2*)&sW[lane][2 * w];
    float2 d1 = *(const float2*)&sW[lane + 32][2 * w];
    float2 ds = make_float2(d0.x + d1.x, d0.y + d1.y);
#pragma unroll
    for (int off = 16; off; off >>= 1) {
        ds.x += __shfl_xor_sync(FULL, ds.x, off);
        ds.y += __shfl_xor_sync(FULL, ds.y, off);
    }
    if (lane == 0) *(float2*)&sDen[2 * w] = ds;

    // Phase B: warp w accumulates slots j % 2 == w, 4-deep batches
    int nw = (cnt > w) ? ((cnt - w + 1) >> 1) : 0;
    int laneoff = lane * 4;
    float4 acc = make_float4(0, 0, 0, 0);
    int i = 0;
    for (; i + 4 <= nw; i += 4) {
        int   o[4];
        float wt[4];
        uint2 v[4];
#pragma unroll
        for (int q = 0; q < 4; q++) {
            int slot = w + (i + q) * 2;
            o[q] = sOff[slot];
            wt[q] = sW[slot][hd];
        }
#pragma unroll
        for (int q = 0; q < 4; q++)
            v[q] = *(const uint2*)&g_hproj16[o[q] + laneoff];
#pragma unroll
        for (int q = 0; q < 4; q++) {
            float2 f01 = __half22float2(*(__half2*)&v[q].x);
            float2 f23 = __half22float2(*(__half2*)&v[q].y);
            acc.x = fmaf(wt[q], f01.x, acc.x);
            acc.y = fmaf(wt[q], f01.y, acc.y);
            acc.z = fmaf(wt[q], f23.x, acc.z);
            acc.w = fmaf(wt[q], f23.y, acc.w);
        }
    }
    for (; i < nw; i++) {
        int slot = w + i * 2;
        int o = sOff[slot];
        float wt = sW[slot][hd];
        uint2 raw = *(const uint2*)&g_hproj16[o + laneoff];
        float2 f01 = __half22float2(*(__half2*)&raw.x);
        float2 f23 = __half22float2(*(__half2*)&raw.y);
        acc.x = fmaf(wt, f01.x, acc.x);
        acc.y = fmaf(wt, f01.y, acc.y);
        acc.z = fmaf(wt, f23.x, acc.z);
        acc.w = fmaf(wt, f23.y, acc.w);
    }
    *(float4*)&sAcc[w][laneoff] = acc;
    __syncthreads();

    // epilogue: thread tid -> channels {2*tid, 2*tid+1} (same head), float2 store
    int ch = tid * 2;
    float2 p0 = *(const float2*)&sAcc[0][ch];
    float2 p1 = *(const float2*)&sAcc[1][ch];
    float inv = 1.0f / fmaxf(sDen[ch >> 5], 1e-16f);
    float2 r;
    r.x = (p0.x + p1.x) * inv;
    r.y = (p0.y + p1.y) * inv;
    r.x = r.x > 0.0f ? r.x : (__expf(r.x) - 1.0f);
    r.y = r.y > 0.0f ? r.y : (__expf(r.y) - 1.0f);
    *(float2*)&out[node * CC + ch] = r;
}

extern "C" void kernel_launch(void* const* d_in, const int* in_sizes, int n_in,
                              void* d_out, int out_size) {
    const float* h  = (const float*)d_in[0];
    const int*   ei = (const int*)d_in[1];
    const float* W  = (const float*)d_in[2];
    const float* a  = (const float*)d_in[3];
    float* out = (float*)d_out;

    k_fused<<<NSCAT + NPROJ, 256>>>(h, ei, W, a);
    k_gat<<<NN, 64>>>(out);
}